// round 4
// baseline (speedup 1.0000x reference)
#include <cuda_runtime.h>
#include <math.h>

#define KNOTS 64
#define WCOLS 7168          // 7 paths * 32 u * 32 w
#define MAXN  4096
#define MAXE  32768
#define NBLK  (MAXE / 8 + KNOTS)   // 4160 padded edge-blocks max

typedef unsigned long long ull;

// ---------------- scratch (device globals; no allocation allowed) ----------------
__device__ float2 g_wtab[(size_t)KNOTS * WCOLS];  // fp32 table, DUPLICATED (v,v), scales folded
__device__ float  g_nodeacc[MAXN * 161];          // 160 sums + 1 count per node
__device__ int    g_binCount[KNOTS];
__device__ int    g_binCursor[KNOTS];
__device__ int    g_perm[NBLK * 8];               // padded, -1 = empty slot
__device__ int    g_blockCell[NBLK];              // -1 = inactive block

// ---------------- f32x2 helpers ----------------
__device__ __forceinline__ ull pk2(float lo, float hi) {
    ull r; asm("mov.b64 %0, {%1, %2};" : "=l"(r) : "f"(lo), "f"(hi)); return r;
}
__device__ __forceinline__ void upk2(ull v, float& lo, float& hi) {
    asm("mov.b64 {%0, %1}, %2;" : "=f"(lo), "=f"(hi) : "l"(v));
}
__device__ __forceinline__ void fma2(ull& d, ull a, ull b) {
    asm("fma.rn.f32x2 %0, %1, %2, %0;" : "+l"(d) : "l"(a), "l"(b));
}
__device__ __forceinline__ ull mul2(ull a, ull b) {
    ull r; asm("mul.rn.f32x2 %0, %1, %2;" : "=l"(r) : "l"(a), "l"(b)); return r;
}

__device__ __forceinline__ int cell_of(float L) {
    float t = L * ((float)(KNOTS - 1) / 5.0f);
    int i = (int)floorf(t);
    if (i < 0) i = 0;
    if (i > KNOTS - 2) i = KNOTS - 2;
    return i;
}

// ---------------- kernel 0: zero / init everything ----------------
__global__ void k_zero(int accTotal) {
    int i = blockIdx.x * blockDim.x + threadIdx.x;
    if (i < accTotal) g_nodeacc[i] = 0.0f;
    if (i < KNOTS)    g_binCount[i] = 0;
    if (i < NBLK * 8) g_perm[i] = -1;
    if (i < NBLK)     g_blockCell[i] = -1;
}

// ---------------- kernel 1: build fp32 dup table + edge histogram ----------------
// Grid (4, 28), block 256. Each block: 16 knots x 256 cols. Hist folded in.
__global__ void k_build(const float* __restrict__ Wfc1, const float* __restrict__ Wfc2,
                        const float* __restrict__ len, int E) {
    __shared__ float sm_h[64][17];
    const int t = threadIdx.x;
    const int kbase = blockIdx.x * 16;
    const int col = blockIdx.y * 256 + t;

    // folded histogram (independent of table work)
    {
        int gid = (blockIdx.y * gridDim.x + blockIdx.x) * 256 + t;
        int stride = gridDim.x * gridDim.y * 256;
        for (int e = gid; e < E; e += stride)
            atomicAdd(&g_binCount[cell_of(len[e])], 1);
    }

    // phase 1: h for 16 knots
    for (int idx = t; idx < 16 * 64; idx += 256) {
        int kk = idx >> 6, c = idx & 63;
        float r = (float)(kbase + kk) * (5.0f / (float)(KNOTS - 1));
        float pre = 0.0f;
        #pragma unroll
        for (int j = 0; j < 8; j++) {
            float d = r - (float)j * (5.0f / 7.0f);
            float rad = expf(-d * d * 0.98f);
            pre += rad * Wfc1[j * 64 + c];
        }
        pre *= 0.35355339059327373f;                 // 1/sqrt(8)
        sm_h[c][kk] = pre / (1.0f + expf(-pre));     // silu
    }
    __syncthreads();

    // phase 2: GEMM h[16,64] @ Wfc2[64,col]
    float acc[16];
    #pragma unroll
    for (int kk = 0; kk < 16; kk++) acc[kk] = 0.0f;
    #pragma unroll 4
    for (int c = 0; c < 64; c++) {
        float wv = __ldg(&Wfc2[c * WCOLS + col]);
        #pragma unroll
        for (int kk = 0; kk < 16; kk++) acc[kk] = fmaf(sm_h[c][kk], wv, acc[kk]);
    }
    float sc = (col < 4096) ? 0.015625f : 0.022097086912079608f;  // (1/8)*A0 or (1/8-norm)*A1
    #pragma unroll
    for (int kk = 0; kk < 16; kk++) {
        float v = acc[kk] * sc;
        g_wtab[(size_t)(kbase + kk) * WCOLS + col] = make_float2(v, v);
    }
}

// ---------------- kernel 2: scan -> padded block layout ----------------
// 1 warp. blocks_c = ceil(cnt/8); cursor[c] = blockstart*8; blockCell filled.
__global__ void k_scan() {
    int t = threadIdx.x;
    int c0 = 2 * t, c1 = 2 * t + 1;
    int n0 = g_binCount[c0], n1 = g_binCount[c1];
    int b0 = (n0 + 7) >> 3, b1 = (n1 + 7) >> 3;
    int s = b0 + b1;
    int x = s;
    #pragma unroll
    for (int o = 1; o < 32; o <<= 1) {
        int y = __shfl_up_sync(0xffffffffu, x, o);
        if (t >= o) x += y;
    }
    int excl = x - s;          // block start of c0
    g_binCursor[c0] = excl * 8;
    g_binCursor[c1] = (excl + b0) * 8;
    for (int i = 0; i < b0; i++) g_blockCell[excl + i] = c0;
    for (int i = 0; i < b1; i++) g_blockCell[excl + b0 + i] = c1;
}

// ---------------- kernel 3: scatter ----------------
__global__ void k_scatter(const float* __restrict__ len, int E) {
    int e = blockIdx.x * blockDim.x + threadIdx.x;
    if (e >= E) return;
    int pos = atomicAdd(&g_binCursor[cell_of(len[e])], 1);
    g_perm[pos] = e;
}

// ---------------- kernel 4: main edge kernel (shared-weight mini-GEMM) ----------------
// CTA = 8 edges of ONE cell. 256 threads = 32 w-cols x 8 u-parts.
// Edges packed pairwise into f32x2 lanes; weights loaded once per CTA as dup float2.
__global__ __launch_bounds__(256, 2) void k_edge(
        const float* __restrict__ x, const float* __restrict__ attr,
        const float* __restrict__ len, const int* __restrict__ src,
        const int* __restrict__ dst, int E) {
    __shared__ ull  sF[11 * 32 * 4];   // [feat][u][epair] : 11264 B
    __shared__ ull  sRed[5 * 32 * 4];  // [out][w][epair]  : 5120 B
    __shared__ int   sEdge[8];
    __shared__ int   sDst[8];
    __shared__ float sFvals[8];
    __shared__ ull   sGm[4], sFm[4];

    const int b = blockIdx.x;
    const int cell = g_blockCell[b];
    if (cell < 0) return;
    const int t = threadIdx.x;
    const int el = t >> 5, u = t & 31;

    // ---- phase A1: per-edge metadata ----
    if (t < 8) {
        int ee = g_perm[b * 8 + t];
        sEdge[t] = ee;
        float fv = 0.0f; int dd = 0;
        if (ee >= 0) {
            dd = dst[ee];
            float tp = len[ee] * ((float)(KNOTS - 1) / 5.0f);
            fv = fminf(fmaxf(tp - (float)cell, 0.0f), 1.0f);
        }
        sDst[t] = dd; sFvals[t] = fv;
    }
    {   // zero reduction buffer
        float* rz = (float*)sRed;
        for (int i = t; i < 5 * 32 * 4 * 2; i += 256) rz[i] = 0.0f;
    }
    __syncthreads();
    if (t < 4) {
        sGm[t] = pk2(1.0f - sFvals[2 * t], 1.0f - sFvals[2 * t + 1]);
        sFm[t] = pk2(sFvals[2 * t], sFvals[2 * t + 1]);
    }

    // ---- phase A2: features for (edge el, u) ----
    {
        int e = sEdge[el];
        float F[11];
        #pragma unroll
        for (int k = 0; k < 11; k++) F[k] = 0.0f;
        if (e >= 0) {
            int sn = src[e];
            const float* ar = attr + e * 9;
            float y0  = ar[0];
            float y10 = ar[1], y11 = ar[2], y12 = ar[3];
            float y20 = ar[4], y21 = ar[5], y22 = ar[6], y23 = ar[7], y24 = ar[8];
            const float cA = 0.31622776601683794f;   // 1/sqrt(10)
            const float cB = 0.18257418583505536f;   // 1/sqrt(30)
            const float cC = 0.36514837167011072f;   // 2/sqrt(30)
            float M00 = -cB * y22 + cA * y24;
            float M01 =  cA * y20,  M02 = cA * y23;
            float M10 =  cA * y20,  M11 = -cB * y22 - cA * y24, M12 = cA * y21;
            float M20 =  cA * y23,  M21 = cA * y21,             M22 = cC * y22;
            const float* xr = x + (size_t)sn * 128;
            float sj = xr[u];
            float v0 = xr[32 + 3 * u], v1 = xr[33 + 3 * u], v2 = xr[34 + 3 * u];
            const float IS3 = 0.5773502691896258f;
            F[0] = sj * y0;
            F[1] = (v0 * y10 + v1 * y11 + v2 * y12) * IS3;
            float sy = sj * IS3;
            F[2] = sy * y10; F[3] = sy * y11; F[4] = sy * y12;
            float yv = y0 * IS3;
            F[5] = v0 * yv; F[6] = v1 * yv; F[7] = v2 * yv;
            F[8]  = v0 * M00 + v1 * M10 + v2 * M20;
            F[9]  = v0 * M01 + v1 * M11 + v2 * M21;
            F[10] = v0 * M02 + v1 * M12 + v2 * M22;
        }
        float* fb = (float*)sF + (u * 4 + (el >> 1)) * 2 + (el & 1);
        #pragma unroll
        for (int k = 0; k < 11; k++) fb[k * 256] = F[k];
    }
    __syncthreads();

    // ---- phase B: mini-GEMM. thread = (w = t&31, part p = t>>5), u in {4p..4p+3} ----
    const int w = t & 31, p = t >> 5;
    const ull* R0 = (const ull*)g_wtab + (size_t)cell * WCOLS;
    const ull* R1 = R0 + WCOLS;

    ull aS0[4], aS1[4], aG0[4], aG1[4], aV0k[3][4], aV1k[3][4];
    #pragma unroll
    for (int q = 0; q < 4; q++) {
        aS0[q] = 0; aS1[q] = 0; aG0[q] = 0; aG1[q] = 0;
        #pragma unroll
        for (int k = 0; k < 3; k++) { aV0k[k][q] = 0; aV1k[k][q] = 0; }
    }

    #pragma unroll
    for (int i = 0; i < 4; i++) {
        const int uu = p * 4 + i;
        const int cb = uu * 32 + w;
        const ull* Fu = sF + uu * 4;   // Fu[feat*128 + pair]
        ull wa, wb;
        // path0 -> S (feat 0)
        wa = R0[cb]; wb = R1[cb];
        #pragma unroll
        for (int q = 0; q < 4; q++) { ull f = Fu[0 * 128 + q]; fma2(aS0[q], f, wa); fma2(aS1[q], f, wb); }
        // path1 -> S (feat 1)
        wa = R0[1024 + cb]; wb = R1[1024 + cb];
        #pragma unroll
        for (int q = 0; q < 4; q++) { ull f = Fu[1 * 128 + q]; fma2(aS0[q], f, wa); fma2(aS1[q], f, wb); }
        // path2 -> G (feat 0)
        wa = R0[2048 + cb]; wb = R1[2048 + cb];
        #pragma unroll
        for (int q = 0; q < 4; q++) { ull f = Fu[0 * 128 + q]; fma2(aG0[q], f, wa); fma2(aG1[q], f, wb); }
        // path3 -> G (feat 1)
        wa = R0[3072 + cb]; wb = R1[3072 + cb];
        #pragma unroll
        for (int q = 0; q < 4; q++) { ull f = Fu[1 * 128 + q]; fma2(aG0[q], f, wa); fma2(aG1[q], f, wb); }
        // path4 -> V[k] (feats 2..4)
        wa = R0[4096 + cb]; wb = R1[4096 + cb];
        #pragma unroll
        for (int k = 0; k < 3; k++)
            #pragma unroll
            for (int q = 0; q < 4; q++) { ull f = Fu[(2 + k) * 128 + q]; fma2(aV0k[k][q], f, wa); fma2(aV1k[k][q], f, wb); }
        // path5 -> V[k] (feats 5..7)
        wa = R0[5120 + cb]; wb = R1[5120 + cb];
        #pragma unroll
        for (int k = 0; k < 3; k++)
            #pragma unroll
            for (int q = 0; q < 4; q++) { ull f = Fu[(5 + k) * 128 + q]; fma2(aV0k[k][q], f, wa); fma2(aV1k[k][q], f, wb); }
        // path6 -> V[k] (feats 8..10)
        wa = R0[6144 + cb]; wb = R1[6144 + cb];
        #pragma unroll
        for (int k = 0; k < 3; k++)
            #pragma unroll
            for (int q = 0; q < 4; q++) { ull f = Fu[(8 + k) * 128 + q]; fma2(aV0k[k][q], f, wa); fma2(aV1k[k][q], f, wb); }
    }

    // ---- phase C: combine lerp banks, reduce across parts via smem atomics ----
    #pragma unroll
    for (int q = 0; q < 4; q++) {
        ull gm = sGm[q], fm = sFm[q];
        float lo, hi;
        float* rb;
        ull m;
        m = mul2(gm, aS0[q]);  fma2(m, fm, aS1[q]);  upk2(m, lo, hi);
        rb = (float*)&sRed[0 * 128 + w * 4 + q]; atomicAdd(rb, lo); atomicAdd(rb + 1, hi);
        m = mul2(gm, aG0[q]);  fma2(m, fm, aG1[q]);  upk2(m, lo, hi);
        rb = (float*)&sRed[1 * 128 + w * 4 + q]; atomicAdd(rb, lo); atomicAdd(rb + 1, hi);
        #pragma unroll
        for (int k = 0; k < 3; k++) {
            m = mul2(gm, aV0k[k][q]); fma2(m, fm, aV1k[k][q]); upk2(m, lo, hi);
            rb = (float*)&sRed[(2 + k) * 128 + w * 4 + q]; atomicAdd(rb, lo); atomicAdd(rb + 1, hi);
        }
    }
    __syncthreads();

    // ---- phase D: output. thread = (edge el, w) ----
    {
        int e = sEdge[el];
        if (e >= 0) {
            float* na = g_nodeacc + (size_t)sDst[el] * 161;
            int pr = el >> 1, c = el & 1;
            const float* rr = (const float*)sRed;
            float S  = rr[(0 * 128 + w * 4 + pr) * 2 + c];
            float G  = rr[(1 * 128 + w * 4 + pr) * 2 + c];
            float V0 = rr[(2 * 128 + w * 4 + pr) * 2 + c];
            float V1 = rr[(3 * 128 + w * 4 + pr) * 2 + c];
            float V2 = rr[(4 * 128 + w * 4 + pr) * 2 + c];
            atomicAdd(na + w,              S);
            atomicAdd(na + 32 + w,         G);
            atomicAdd(na + 64 + 3 * w + 0, V0);
            atomicAdd(na + 64 + 3 * w + 1, V1);
            atomicAdd(na + 64 + 3 * w + 2, V2);
            if (w == 0) atomicAdd(na + 160, 1.0f);
        }
    }
}

// ---------------- node kernel: mean, gating, self-connection, norms ----------------
__global__ void k_node(const float* __restrict__ x, const float* __restrict__ Wss,
                       const float* __restrict__ Wsv, float* __restrict__ out, int N) {
    __shared__ float sx[8][128];
    const int warp = threadIdx.x >> 5, lane = threadIdx.x & 31;
    int n = blockIdx.x * 8 + warp;
    if (n >= N) return;

    const float4* xr = reinterpret_cast<const float4*>(x + (size_t)n * 128);
    reinterpret_cast<float4*>(&sx[warp][0])[lane] = xr[lane];
    __syncwarp();

    const float* na = g_nodeacc + (size_t)n * 161;
    float inv = 1.0f / fmaxf(na[160], 1.0f);
    float ms  = na[lane] * inv;
    float mg  = na[32 + lane] * inv;
    float mv0 = na[64 + 3 * lane + 0] * inv;
    float mv1 = na[64 + 3 * lane + 1] * inv;
    float mv2 = na[64 + 3 * lane + 2] * inv;

    float gs   = ms / (1.0f + expf(-ms));
    float gate = 1.0f / (1.0f + expf(-mg));
    float gv0 = mv0 * gate, gv1 = mv1 * gate, gv2 = mv2 * gate;

    float ds = 0.f, dv0 = 0.f, dv1 = 0.f, dv2 = 0.f;
    #pragma unroll 4
    for (int u = 0; u < 32; u++) {
        float su  = sx[warp][u];
        float vu0 = sx[warp][32 + 3 * u], vu1 = sx[warp][33 + 3 * u], vu2 = sx[warp][34 + 3 * u];
        float a = __ldg(&Wss[u * 32 + lane]);
        float bb = __ldg(&Wsv[u * 32 + lane]);
        ds  = fmaf(su,  a, ds);
        dv0 = fmaf(vu0, bb, dv0);
        dv1 = fmaf(vu1, bb, dv1);
        dv2 = fmaf(vu2, bb, dv2);
    }
    const float ism = 0.17677669529663687f;   // 1/sqrt(32)
    float hs  = gs  + ds  * ism;
    float hv0 = gv0 + dv0 * ism;
    float hv1 = gv1 + dv1 * ism;
    float hv2 = gv2 + dv2 * ism;

    out[(size_t)n * 64 + lane]      = sqrtf(hs * hs + 1e-12f);
    out[(size_t)n * 64 + 32 + lane] = sqrtf(hv0 * hv0 + hv1 * hv1 + hv2 * hv2 + 1e-12f);
}

// ---------------- launch ----------------
extern "C" void kernel_launch(void* const* d_in, const int* in_sizes, int n_in,
                              void* d_out, int out_size) {
    const float* x    = (const float*)d_in[0];
    const float* attr = (const float*)d_in[1];
    const float* len  = (const float*)d_in[2];
    const int*   src  = (const int*)d_in[3];
    const int*   dst  = (const int*)d_in[4];
    const float* Wfc1 = (const float*)d_in[5];
    const float* Wfc2 = (const float*)d_in[6];
    const float* Wss  = (const float*)d_in[7];
    const float* Wsv  = (const float*)d_in[8];
    float* out = (float*)d_out;

    int N = in_sizes[0] / 128;
    int E = in_sizes[2];

    int zt = N * 161;                     // largest init range
    k_zero<<<(zt + 255) / 256, 256>>>(N * 161);
    dim3 bgrid(KNOTS / 16, 28);
    k_build<<<bgrid, 256>>>(Wfc1, Wfc2, len, E);
    k_scan<<<1, 32>>>();
    k_scatter<<<(E + 255) / 256, 256>>>(len, E);
    k_edge<<<NBLK, 256>>>(x, attr, len, src, dst, E);
    k_node<<<(N + 7) / 8, 256>>>(x, Wss, Wsv, out, N);
}

// round 5
// speedup vs baseline: 2.0132x; 2.0132x over previous
#include <cuda_runtime.h>
#include <cuda_fp16.h>
#include <math.h>

#define KNOTS 64
#define WCOLS 7168          // 7 paths * 32 u * 32 w
#define MAXN  4096
#define MAXE  32768

// ---------------- scratch (device globals; no allocation allowed) ----------------
__device__ unsigned short g_wtab_raw[(size_t)KNOTS * WCOLS];  // fp16 table, scales folded in
__device__ float g_nodeacc[MAXN * 161];           // 160 sums + 1 count per node
__device__ int   g_binCount[KNOTS];               // zero-init at load; self-resetting per launch
__device__ int   g_binCursor[KNOTS];
__device__ int   g_perm[MAXE];

// ---------------- f32x2 helpers ----------------
__device__ __forceinline__ unsigned long long pk2(float lo, float hi) {
    unsigned long long r;
    asm("mov.b64 %0, {%1, %2};" : "=l"(r) : "f"(lo), "f"(hi));
    return r;
}
__device__ __forceinline__ void upk2(unsigned long long v, float& lo, float& hi) {
    asm("mov.b64 {%0, %1}, %2;" : "=f"(lo), "=f"(hi) : "l"(v));
}
__device__ __forceinline__ void fma2(unsigned long long& d, unsigned long long a, unsigned long long b) {
    asm("fma.rn.f32x2 %0, %1, %2, %0;" : "+l"(d) : "l"(a), "l"(b));
}
__device__ __forceinline__ unsigned long long mul2(unsigned long long a, unsigned long long b) {
    unsigned long long r;
    asm("mul.rn.f32x2 %0, %1, %2;" : "=l"(r) : "l"(a), "l"(b));
    return r;
}

__device__ __forceinline__ int cell_of(float L) {
    float t = L * ((float)(KNOTS - 1) / 5.0f);
    int i = (int)floorf(t);
    if (i < 0) i = 0;
    if (i > KNOTS - 2) i = KNOTS - 2;
    return i;
}

// ---------------- kernel 1: build fp16 W(r) table + low-contention histogram ----------------
// Grid (4, 28), block 256. Each block: 16 knots x 256 cols. Smem-aggregated hist folded in.
__global__ void k_build(const float* __restrict__ Wfc1, const float* __restrict__ Wfc2,
                        const float* __restrict__ len, int E) {
    __shared__ float sm_h[64][17];   // [c][knot-in-group], padded
    __shared__ int   sm_hist[KNOTS];
    const int t = threadIdx.x;       // 256 threads
    const int kbase = blockIdx.x * 16;
    const int col = blockIdx.y * 256 + t;

    if (t < KNOTS) sm_hist[t] = 0;
    __syncthreads();

    // folded histogram: smem aggregate, then 64 global atomics per CTA
    {
        int gid = (blockIdx.y * gridDim.x + blockIdx.x) * 256 + t;
        int stride = gridDim.x * gridDim.y * 256;
        for (int e = gid; e < E; e += stride)
            atomicAdd(&sm_hist[cell_of(len[e])], 1);
    }

    // phase 1: h for 16 knots
    for (int idx = t; idx < 16 * 64; idx += 256) {
        int kk = idx >> 6, c = idx & 63;
        float r = (float)(kbase + kk) * (5.0f / (float)(KNOTS - 1));
        float pre = 0.0f;
        #pragma unroll
        for (int j = 0; j < 8; j++) {
            float d = r - (float)j * (5.0f / 7.0f);
            float rad = expf(-d * d * 0.98f);          // 1/(2*sigma^2) = 49/50
            pre += rad * Wfc1[j * 64 + c];
        }
        pre *= 0.35355339059327373f;                    // 1/sqrt(8)
        sm_h[c][kk] = pre / (1.0f + expf(-pre));        // silu
    }
    __syncthreads();

    if (t < KNOTS && sm_hist[t] > 0) atomicAdd(&g_binCount[t], sm_hist[t]);

    // phase 2: GEMM h[16,64] @ Wfc2[64, col]
    float acc[16];
    #pragma unroll
    for (int kk = 0; kk < 16; kk++) acc[kk] = 0.0f;
    #pragma unroll 4
    for (int c = 0; c < 64; c++) {
        float wv = __ldg(&Wfc2[c * WCOLS + col]);
        #pragma unroll
        for (int kk = 0; kk < 16; kk++) acc[kk] = fmaf(sm_h[c][kk], wv, acc[kk]);
    }
    // (1/8 weight-norm) * (A0 or A1)
    float sc = (col < 4096) ? 0.015625f : 0.022097086912079608f;
    #pragma unroll
    for (int kk = 0; kk < 16; kk++)
        g_wtab_raw[(size_t)(kbase + kk) * WCOLS + col] =
            __half_as_ushort(__float2half_rn(acc[kk] * sc));
}

// ---------------- kernel 2: scan (1 warp, 64 bins) + self-reset of binCount ----------------
__global__ void k_scan() {
    int t = threadIdx.x;
    int v0 = g_binCount[2 * t], v1 = g_binCount[2 * t + 1];
    int s = v0 + v1;
    int x = s;
    #pragma unroll
    for (int o = 1; o < 32; o <<= 1) {
        int y = __shfl_up_sync(0xffffffffu, x, o);
        if (t >= o) x += y;
    }
    int excl = x - s;
    g_binCursor[2 * t]     = excl;
    g_binCursor[2 * t + 1] = excl + v0;
    // reset for next graph replay (all reads above complete in this warp)
    g_binCount[2 * t] = 0;
    g_binCount[2 * t + 1] = 0;
}

// ---------------- kernel 3: two-level scatter + nodeacc zeroing ----------------
__global__ void k_scatterzero(const float* __restrict__ len, int E, int accTotal) {
    __shared__ int sCnt[KNOTS];
    __shared__ int sBase[KNOTS];
    const int t = threadIdx.x;
    const int gid = blockIdx.x * 256 + t;

    if (t < KNOTS) sCnt[t] = 0;

    // folded zeroing of node accumulators
    for (int i = gid; i < accTotal; i += gridDim.x * 256) g_nodeacc[i] = 0.0f;
    __syncthreads();

    int e = -1, bin = 0, rank = 0;
    if (gid < E) {
        e = gid;
        bin = cell_of(len[e]);
        rank = atomicAdd(&sCnt[bin], 1);
    }
    __syncthreads();
    if (t < KNOTS) sBase[t] = (sCnt[t] > 0) ? atomicAdd(&g_binCursor[t], sCnt[t]) : 0;
    __syncthreads();
    if (e >= 0) g_perm[sBase[bin] + rank] = e;
}

// ---------------- kernel 4 (profiled slot): main edge kernel ----------------
// 1 warp per edge; lane = (wg = lane&7 -> 4 consecutive w; us = lane>>3 -> u stride 4).
// fp16 table, deferred lerp (two acc banks), f32x2 FMA.
__global__ __launch_bounds__(256, 2) void k_edge(
        const float* __restrict__ x, const float* __restrict__ attr,
        const float* __restrict__ len, const int* __restrict__ src,
        const int* __restrict__ dst, int E) {
    __shared__ float2 tf2[8][32][11];   // features pre-duplicated as (v,v)
    const int warp = threadIdx.x >> 5, lane = threadIdx.x & 31;
    int eidx = blockIdx.x * 8 + warp;
    if (eidx >= E) return;
    int e = g_perm[eidx];

    int sn = src[e], dn = dst[e];
    float L = len[e];
    const float* ar = attr + e * 9;
    float y0  = ar[0];
    float y10 = ar[1], y11 = ar[2], y12 = ar[3];
    float y20 = ar[4], y21 = ar[5], y22 = ar[6], y23 = ar[7], y24 = ar[8];

    // M[i][k] = sum_m C121[i,m,k]*y2[m]  (constants folded)
    const float cA = 0.31622776601683794f;   // 1/sqrt(10)
    const float cB = 0.18257418583505536f;   // 1/sqrt(30)
    const float cC = 0.36514837167011072f;   // 2/sqrt(30)
    float M00 = -cB * y22 + cA * y24;
    float M01 =  cA * y20,  M02 = cA * y23;
    float M10 =  cA * y20,  M11 = -cB * y22 - cA * y24, M12 = cA * y21;
    float M20 =  cA * y23,  M21 = cA * y21,             M22 = cC * y22;

    // t-features: lane = u for this phase
    const float* xr = x + (size_t)sn * 128;
    float sj = xr[lane];
    float v0 = xr[32 + 3 * lane], v1 = xr[33 + 3 * lane], v2 = xr[34 + 3 * lane];
    const float IS3 = 0.5773502691896258f;
    float2* tr = &tf2[warp][lane][0];
    float t00 = sj * y0;
    float t11 = (v0 * y10 + v1 * y11 + v2 * y12) * IS3;
    tr[0] = make_float2(t00, t00);
    tr[1] = make_float2(t11, t11);
    float sy = sj * IS3;
    tr[2] = make_float2(sy * y10, sy * y10);
    tr[3] = make_float2(sy * y11, sy * y11);
    tr[4] = make_float2(sy * y12, sy * y12);
    float yv = y0 * IS3;
    tr[5] = make_float2(v0 * yv, v0 * yv);
    tr[6] = make_float2(v1 * yv, v1 * yv);
    tr[7] = make_float2(v2 * yv, v2 * yv);
    float t12a = v0 * M00 + v1 * M10 + v2 * M20;
    float t12b = v0 * M01 + v1 * M11 + v2 * M21;
    float t12c = v0 * M02 + v1 * M12 + v2 * M22;
    tr[8]  = make_float2(t12a, t12a);
    tr[9]  = make_float2(t12b, t12b);
    tr[10] = make_float2(t12c, t12c);
    __syncwarp();

    // interpolation setup (uniform across warp)
    float tp = L * ((float)(KNOTS - 1) / 5.0f);
    int ci = (int)floorf(tp);
    if (ci < 0) ci = 0;
    if (ci > KNOTS - 2) ci = KNOTS - 2;
    float f = tp - (float)ci;
    const __half* wt = reinterpret_cast<const __half*>(g_wtab_raw);
    const __half* r0 = wt + (size_t)ci * WCOLS;
    const __half* r1 = r0 + WCOLS;

    const int wg = lane & 7, us = lane >> 3;
    const int wb = wg * 4;

    // accumulators: [bank(knot)][col-pair]
    unsigned long long aS[2][2]  = {{0ull,0ull},{0ull,0ull}};
    unsigned long long aG[2][2]  = {{0ull,0ull},{0ull,0ull}};
    unsigned long long aV[3][2][2] = {{{0ull,0ull},{0ull,0ull}},
                                      {{0ull,0ull},{0ull,0ull}},
                                      {{0ull,0ull},{0ull,0ull}}};

    #pragma unroll 2
    for (int j = 0; j < 8; j++) {
        int u = 4 * j + us;
        const unsigned long long* Fv =
            reinterpret_cast<const unsigned long long*>(&tf2[warp][u][0]);
        int ub = u * 32 + wb;
        const __half* p0 = r0 + ub;
        const __half* p1 = r1 + ub;
        unsigned long long A0, A1, B0, B1, F;

#define LOADP(P)                                                                  \
        {                                                                         \
            uint2 _a = *reinterpret_cast<const uint2*>(p0 + (P) * 1024);          \
            uint2 _b = *reinterpret_cast<const uint2*>(p1 + (P) * 1024);          \
            float2 _f;                                                            \
            _f = __half22float2(*reinterpret_cast<const __half2*>(&_a.x)); A0 = pk2(_f.x, _f.y); \
            _f = __half22float2(*reinterpret_cast<const __half2*>(&_a.y)); A1 = pk2(_f.x, _f.y); \
            _f = __half22float2(*reinterpret_cast<const __half2*>(&_b.x)); B0 = pk2(_f.x, _f.y); \
            _f = __half22float2(*reinterpret_cast<const __half2*>(&_b.y)); B1 = pk2(_f.x, _f.y); \
        }

        LOADP(0); F = Fv[0];
        fma2(aS[0][0], F, A0); fma2(aS[0][1], F, A1);
        fma2(aS[1][0], F, B0); fma2(aS[1][1], F, B1);
        LOADP(1); F = Fv[1];
        fma2(aS[0][0], F, A0); fma2(aS[0][1], F, A1);
        fma2(aS[1][0], F, B0); fma2(aS[1][1], F, B1);
        LOADP(2); F = Fv[0];
        fma2(aG[0][0], F, A0); fma2(aG[0][1], F, A1);
        fma2(aG[1][0], F, B0); fma2(aG[1][1], F, B1);
        LOADP(3); F = Fv[1];
        fma2(aG[0][0], F, A0); fma2(aG[0][1], F, A1);
        fma2(aG[1][0], F, B0); fma2(aG[1][1], F, B1);
        LOADP(4);
        F = Fv[2]; fma2(aV[0][0][0], F, A0); fma2(aV[0][0][1], F, A1);
                   fma2(aV[0][1][0], F, B0); fma2(aV[0][1][1], F, B1);
        F = Fv[3]; fma2(aV[1][0][0], F, A0); fma2(aV[1][0][1], F, A1);
                   fma2(aV[1][1][0], F, B0); fma2(aV[1][1][1], F, B1);
        F = Fv[4]; fma2(aV[2][0][0], F, A0); fma2(aV[2][0][1], F, A1);
                   fma2(aV[2][1][0], F, B0); fma2(aV[2][1][1], F, B1);
        LOADP(5);
        F = Fv[5]; fma2(aV[0][0][0], F, A0); fma2(aV[0][0][1], F, A1);
                   fma2(aV[0][1][0], F, B0); fma2(aV[0][1][1], F, B1);
        F = Fv[6]; fma2(aV[1][0][0], F, A0); fma2(aV[1][0][1], F, A1);
                   fma2(aV[1][1][0], F, B0); fma2(aV[1][1][1], F, B1);
        F = Fv[7]; fma2(aV[2][0][0], F, A0); fma2(aV[2][0][1], F, A1);
                   fma2(aV[2][1][0], F, B0); fma2(aV[2][1][1], F, B1);
        LOADP(6);
        F = Fv[8]; fma2(aV[0][0][0], F, A0); fma2(aV[0][0][1], F, A1);
                   fma2(aV[0][1][0], F, B0); fma2(aV[0][1][1], F, B1);
        F = Fv[9]; fma2(aV[1][0][0], F, A0); fma2(aV[1][0][1], F, A1);
                   fma2(aV[1][1][0], F, B0); fma2(aV[1][1][1], F, B1);
        F = Fv[10]; fma2(aV[2][0][0], F, A0); fma2(aV[2][0][1], F, A1);
                    fma2(aV[2][1][0], F, B0); fma2(aV[2][1][1], F, B1);
#undef LOADP
    }

    // combine banks: m = (1-f)*bank0 + f*bank1
    unsigned long long f2  = pk2(f, f);
    unsigned long long g2  = pk2(1.0f - f, 1.0f - f);
    float S[4], G[4], V[3][4];
    {
        unsigned long long m;
        m = mul2(g2, aS[0][0]); fma2(m, f2, aS[1][0]); upk2(m, S[0], S[1]);
        m = mul2(g2, aS[0][1]); fma2(m, f2, aS[1][1]); upk2(m, S[2], S[3]);
        m = mul2(g2, aG[0][0]); fma2(m, f2, aG[1][0]); upk2(m, G[0], G[1]);
        m = mul2(g2, aG[0][1]); fma2(m, f2, aG[1][1]); upk2(m, G[2], G[3]);
        #pragma unroll
        for (int k = 0; k < 3; k++) {
            m = mul2(g2, aV[k][0][0]); fma2(m, f2, aV[k][1][0]); upk2(m, V[k][0], V[k][1]);
            m = mul2(g2, aV[k][0][1]); fma2(m, f2, aV[k][1][1]); upk2(m, V[k][2], V[k][3]);
        }
    }

#define RED(v)                                                    \
    v += __shfl_down_sync(0xffffffffu, v, 16);                    \
    v += __shfl_down_sync(0xffffffffu, v, 8);
    #pragma unroll
    for (int q = 0; q < 4; q++) {
        RED(S[q]) RED(G[q]) RED(V[0][q]) RED(V[1][q]) RED(V[2][q])
    }

    if (us == 0) {
        float* na = g_nodeacc + (size_t)dn * 161;
        #pragma unroll
        for (int q = 0; q < 4; q++) {
            int w = wb + q;
            atomicAdd(na + w,              S[q]);
            atomicAdd(na + 32 + w,         G[q]);
            atomicAdd(na + 64 + 3 * w + 0, V[0][q]);
            atomicAdd(na + 64 + 3 * w + 1, V[1][q]);
            atomicAdd(na + 64 + 3 * w + 2, V[2][q]);
        }
        if (lane == 0) atomicAdd(na + 160, 1.0f);
    }
}

// ---------------- kernel 5: mean, gating, self-connection, norms ----------------
__global__ void k_node(const float* __restrict__ x, const float* __restrict__ Wss,
                       const float* __restrict__ Wsv, float* __restrict__ out, int N) {
    __shared__ float sx[8][128];
    const int warp = threadIdx.x >> 5, lane = threadIdx.x & 31;
    int n = blockIdx.x * 8 + warp;
    if (n >= N) return;

    const float4* xr = reinterpret_cast<const float4*>(x + (size_t)n * 128);
    reinterpret_cast<float4*>(&sx[warp][0])[lane] = xr[lane];
    __syncwarp();

    const float* na = g_nodeacc + (size_t)n * 161;
    float inv = 1.0f / fmaxf(na[160], 1.0f);
    float ms  = na[lane] * inv;
    float mg  = na[32 + lane] * inv;
    float mv0 = na[64 + 3 * lane + 0] * inv;
    float mv1 = na[64 + 3 * lane + 1] * inv;
    float mv2 = na[64 + 3 * lane + 2] * inv;

    float gs   = ms / (1.0f + expf(-ms));
    float gate = 1.0f / (1.0f + expf(-mg));
    float gv0 = mv0 * gate, gv1 = mv1 * gate, gv2 = mv2 * gate;

    float ds = 0.f, dv0 = 0.f, dv1 = 0.f, dv2 = 0.f;
    #pragma unroll 4
    for (int u = 0; u < 32; u++) {
        float su  = sx[warp][u];
        float vu0 = sx[warp][32 + 3 * u], vu1 = sx[warp][33 + 3 * u], vu2 = sx[warp][34 + 3 * u];
        float a = __ldg(&Wss[u * 32 + lane]);
        float b = __ldg(&Wsv[u * 32 + lane]);
        ds  = fmaf(su,  a, ds);
        dv0 = fmaf(vu0, b, dv0);
        dv1 = fmaf(vu1, b, dv1);
        dv2 = fmaf(vu2, b, dv2);
    }
    const float ism = 0.17677669529663687f;   // 1/sqrt(32)
    float hs  = gs  + ds  * ism;
    float hv0 = gv0 + dv0 * ism;
    float hv1 = gv1 + dv1 * ism;
    float hv2 = gv2 + dv2 * ism;

    out[(size_t)n * 64 + lane]      = sqrtf(hs * hs + 1e-12f);
    out[(size_t)n * 64 + 32 + lane] = sqrtf(hv0 * hv0 + hv1 * hv1 + hv2 * hv2 + 1e-12f);
}

// ---------------- launch ----------------
extern "C" void kernel_launch(void* const* d_in, const int* in_sizes, int n_in,
                              void* d_out, int out_size) {
    const float* x    = (const float*)d_in[0];
    const float* attr = (const float*)d_in[1];
    const float* len  = (const float*)d_in[2];
    const int*   src  = (const int*)d_in[3];
    const int*   dst  = (const int*)d_in[4];
    const float* Wfc1 = (const float*)d_in[5];
    const float* Wfc2 = (const float*)d_in[6];
    const float* Wss  = (const float*)d_in[7];
    const float* Wsv  = (const float*)d_in[8];
    float* out = (float*)d_out;

    int N = in_sizes[0] / 128;
    int E = in_sizes[2];

    dim3 bgrid(KNOTS / 16, 28);
    k_build<<<bgrid, 256>>>(Wfc1, Wfc2, len, E);                 // #1 (table + hist)
    k_scan<<<1, 32>>>();                                         // #2 (scan + bin reset)
    k_scatterzero<<<(E + 255) / 256, 256>>>(len, E, N * 161);    // #3 (scatter + acc zero)
    k_edge<<<(E + 7) / 8, 256>>>(x, attr, len, src, dst, E);     // #4 (profiled slot)
    k_node<<<(N + 7) / 8, 256>>>(x, Wss, Wsv, out, N);           // #5
}

// round 6
// speedup vs baseline: 2.1328x; 1.0594x over previous
#include <cuda_runtime.h>
#include <cuda_fp16.h>
#include <math.h>

#define KNOTS 64
#define WCOLS 7168          // 7 paths * 32 u * 32 w
#define MAXN  4096
#define MAXE  32768

typedef unsigned long long ull;

// ---------------- scratch (device globals; no allocation allowed) ----------------
__device__ unsigned short g_wtab_raw[(size_t)KNOTS * WCOLS];  // fp16 table, scales folded in
__device__ float g_nodeacc[MAXN * 161];           // 160 sums + 1 count per node
__device__ int   g_binCount[KNOTS];               // zero-init at load; self-resetting per launch
__device__ int   g_binCursor[KNOTS];
__device__ int   g_perm[MAXE];

// ---------------- f32x2 helpers ----------------
__device__ __forceinline__ ull pk2(float lo, float hi) {
    ull r; asm("mov.b64 %0, {%1, %2};" : "=l"(r) : "f"(lo), "f"(hi)); return r;
}
__device__ __forceinline__ void upk2(ull v, float& lo, float& hi) {
    asm("mov.b64 {%0, %1}, %2;" : "=f"(lo), "=f"(hi) : "l"(v));
}
__device__ __forceinline__ void fma2(ull& d, ull a, ull b) {
    asm("fma.rn.f32x2 %0, %1, %2, %0;" : "+l"(d) : "l"(a), "l"(b));
}
// w = a + f*(b-a), exact fp32 lerp on a packed pair loaded as fp16x2
__device__ __forceinline__ ull lerp2(unsigned int ha, unsigned int hb, ull f2) {
    float2 fa = __half22float2(*reinterpret_cast<const __half2*>(&ha));
    float2 fb = __half22float2(*reinterpret_cast<const __half2*>(&hb));
    ull A = pk2(fa.x, fa.y);
    ull B = pk2(fb.x, fb.y);
    ull D;
    asm("sub.rn.f32x2 %0, %1, %2;" : "=l"(D) : "l"(B), "l"(A));
    fma2(A, f2, D);
    return A;
}

__device__ __forceinline__ int cell_of(float L) {
    float t = L * ((float)(KNOTS - 1) / 5.0f);
    int i = (int)floorf(t);
    if (i < 0) i = 0;
    if (i > KNOTS - 2) i = KNOTS - 2;
    return i;
}

// ---------------- kernel 1: build fp16 W(r) table + low-contention histogram ----------------
__global__ void k_build(const float* __restrict__ Wfc1, const float* __restrict__ Wfc2,
                        const float* __restrict__ len, int E) {
    __shared__ float sm_h[64][17];
    __shared__ int   sm_hist[KNOTS];
    const int t = threadIdx.x;
    const int kbase = blockIdx.x * 16;
    const int col = blockIdx.y * 256 + t;

    if (t < KNOTS) sm_hist[t] = 0;
    __syncthreads();

    {
        int gid = (blockIdx.y * gridDim.x + blockIdx.x) * 256 + t;
        int stride = gridDim.x * gridDim.y * 256;
        for (int e = gid; e < E; e += stride)
            atomicAdd(&sm_hist[cell_of(len[e])], 1);
    }

    for (int idx = t; idx < 16 * 64; idx += 256) {
        int kk = idx >> 6, c = idx & 63;
        float r = (float)(kbase + kk) * (5.0f / (float)(KNOTS - 1));
        float pre = 0.0f;
        #pragma unroll
        for (int j = 0; j < 8; j++) {
            float d = r - (float)j * (5.0f / 7.0f);
            float rad = expf(-d * d * 0.98f);
            pre += rad * Wfc1[j * 64 + c];
        }
        pre *= 0.35355339059327373f;                    // 1/sqrt(8)
        sm_h[c][kk] = pre / (1.0f + expf(-pre));        // silu
    }
    __syncthreads();

    if (t < KNOTS && sm_hist[t] > 0) atomicAdd(&g_binCount[t], sm_hist[t]);

    float acc[16];
    #pragma unroll
    for (int kk = 0; kk < 16; kk++) acc[kk] = 0.0f;
    #pragma unroll 4
    for (int c = 0; c < 64; c++) {
        float wv = __ldg(&Wfc2[c * WCOLS + col]);
        #pragma unroll
        for (int kk = 0; kk < 16; kk++) acc[kk] = fmaf(sm_h[c][kk], wv, acc[kk]);
    }
    float sc = (col < 4096) ? 0.015625f : 0.022097086912079608f;
    #pragma unroll
    for (int kk = 0; kk < 16; kk++)
        g_wtab_raw[(size_t)(kbase + kk) * WCOLS + col] =
            __half_as_ushort(__float2half_rn(acc[kk] * sc));
}

// ---------------- kernel 2: scan (1 warp, 64 bins) + self-reset of binCount ----------------
__global__ void k_scan() {
    int t = threadIdx.x;
    int v0 = g_binCount[2 * t], v1 = g_binCount[2 * t + 1];
    int s = v0 + v1;
    int x = s;
    #pragma unroll
    for (int o = 1; o < 32; o <<= 1) {
        int y = __shfl_up_sync(0xffffffffu, x, o);
        if (t >= o) x += y;
    }
    int excl = x - s;
    g_binCursor[2 * t]     = excl;
    g_binCursor[2 * t + 1] = excl + v0;
    g_binCount[2 * t] = 0;
    g_binCount[2 * t + 1] = 0;
}

// ---------------- kernel 3: two-level scatter + nodeacc zeroing ----------------
__global__ void k_scatterzero(const float* __restrict__ len, int E, int accTotal) {
    __shared__ int sCnt[KNOTS];
    __shared__ int sBase[KNOTS];
    const int t = threadIdx.x;
    const int gid = blockIdx.x * 256 + t;

    if (t < KNOTS) sCnt[t] = 0;

    for (int i = gid; i < accTotal; i += gridDim.x * 256) g_nodeacc[i] = 0.0f;
    __syncthreads();

    int e = -1, bin = 0, rank = 0;
    if (gid < E) {
        e = gid;
        bin = cell_of(len[e]);
        rank = atomicAdd(&sCnt[bin], 1);
    }
    __syncthreads();
    if (t < KNOTS) sBase[t] = (sCnt[t] > 0) ? atomicAdd(&g_binCursor[t], sCnt[t]) : 0;
    __syncthreads();
    if (e >= 0) g_perm[sBase[bin] + rank] = e;
}

// ---------------- kernel 4 (profiled slot): main edge kernel ----------------
// 1 warp per edge; lane = (wg = lane&7 -> 4 consecutive w; us = lane>>3 -> u stride 4).
// fp16 table, EARLY fp32 lerp, single f32x2 accumulator bank, 3 CTAs/SM.
__global__ __launch_bounds__(256, 3) void k_edge(
        const float* __restrict__ x, const float* __restrict__ attr,
        const float* __restrict__ len, const int* __restrict__ src,
        const int* __restrict__ dst, int E) {
    __shared__ float2 tf2[8][32][11];   // features pre-duplicated as (v,v)
    const int warp = threadIdx.x >> 5, lane = threadIdx.x & 31;
    int eidx = blockIdx.x * 8 + warp;
    if (eidx >= E) return;
    int e = g_perm[eidx];

    int sn = src[e], dn = dst[e];
    float L = len[e];
    const float* ar = attr + e * 9;
    float y0  = ar[0];
    float y10 = ar[1], y11 = ar[2], y12 = ar[3];
    float y20 = ar[4], y21 = ar[5], y22 = ar[6], y23 = ar[7], y24 = ar[8];

    const float cA = 0.31622776601683794f;   // 1/sqrt(10)
    const float cB = 0.18257418583505536f;   // 1/sqrt(30)
    const float cC = 0.36514837167011072f;   // 2/sqrt(30)
    float M00 = -cB * y22 + cA * y24;
    float M01 =  cA * y20,  M02 = cA * y23;
    float M10 =  cA * y20,  M11 = -cB * y22 - cA * y24, M12 = cA * y21;
    float M20 =  cA * y23,  M21 = cA * y21,             M22 = cC * y22;

    const float* xr = x + (size_t)sn * 128;
    float sj = xr[lane];
    float v0 = xr[32 + 3 * lane], v1 = xr[33 + 3 * lane], v2 = xr[34 + 3 * lane];
    const float IS3 = 0.5773502691896258f;
    float2* tr = &tf2[warp][lane][0];
    float t00 = sj * y0;
    float t11 = (v0 * y10 + v1 * y11 + v2 * y12) * IS3;
    tr[0] = make_float2(t00, t00);
    tr[1] = make_float2(t11, t11);
    float sy = sj * IS3;
    tr[2] = make_float2(sy * y10, sy * y10);
    tr[3] = make_float2(sy * y11, sy * y11);
    tr[4] = make_float2(sy * y12, sy * y12);
    float yv = y0 * IS3;
    tr[5] = make_float2(v0 * yv, v0 * yv);
    tr[6] = make_float2(v1 * yv, v1 * yv);
    tr[7] = make_float2(v2 * yv, v2 * yv);
    float t12a = v0 * M00 + v1 * M10 + v2 * M20;
    float t12b = v0 * M01 + v1 * M11 + v2 * M21;
    float t12c = v0 * M02 + v1 * M12 + v2 * M22;
    tr[8]  = make_float2(t12a, t12a);
    tr[9]  = make_float2(t12b, t12b);
    tr[10] = make_float2(t12c, t12c);
    __syncwarp();

    float tp = L * ((float)(KNOTS - 1) / 5.0f);
    int ci = (int)floorf(tp);
    if (ci < 0) ci = 0;
    if (ci > KNOTS - 2) ci = KNOTS - 2;
    float f = tp - (float)ci;
    ull f2 = pk2(f, f);
    const __half* wt = reinterpret_cast<const __half*>(g_wtab_raw);
    const __half* r0 = wt + (size_t)ci * WCOLS;
    const __half* r1 = r0 + WCOLS;

    const int wg = lane & 7, us = lane >> 3;
    const int wb = wg * 4;

    // single accumulator bank: [col-pair]
    ull aS[2]    = {0ull, 0ull};
    ull aG[2]    = {0ull, 0ull};
    ull aV[3][2] = {{0ull,0ull},{0ull,0ull},{0ull,0ull}};

    #pragma unroll 2
    for (int j = 0; j < 8; j++) {
        int u = 4 * j + us;
        const ull* Fv = reinterpret_cast<const ull*>(&tf2[warp][u][0]);
        int ub = u * 32 + wb;
        const __half* p0 = r0 + ub;
        const __half* p1 = r1 + ub;
        ull W0, W1, F;

#define LOADP(P)                                                                  \
        {                                                                         \
            uint2 _a = *reinterpret_cast<const uint2*>(p0 + (P) * 1024);          \
            uint2 _b = *reinterpret_cast<const uint2*>(p1 + (P) * 1024);          \
            W0 = lerp2(_a.x, _b.x, f2);                                           \
            W1 = lerp2(_a.y, _b.y, f2);                                           \
        }

        LOADP(0); F = Fv[0]; fma2(aS[0], F, W0); fma2(aS[1], F, W1);
        LOADP(1); F = Fv[1]; fma2(aS[0], F, W0); fma2(aS[1], F, W1);
        LOADP(2); F = Fv[0]; fma2(aG[0], F, W0); fma2(aG[1], F, W1);
        LOADP(3); F = Fv[1]; fma2(aG[0], F, W0); fma2(aG[1], F, W1);
        LOADP(4);
        F = Fv[2]; fma2(aV[0][0], F, W0); fma2(aV[0][1], F, W1);
        F = Fv[3]; fma2(aV[1][0], F, W0); fma2(aV[1][1], F, W1);
        F = Fv[4]; fma2(aV[2][0], F, W0); fma2(aV[2][1], F, W1);
        LOADP(5);
        F = Fv[5]; fma2(aV[0][0], F, W0); fma2(aV[0][1], F, W1);
        F = Fv[6]; fma2(aV[1][0], F, W0); fma2(aV[1][1], F, W1);
        F = Fv[7]; fma2(aV[2][0], F, W0); fma2(aV[2][1], F, W1);
        LOADP(6);
        F = Fv[8];  fma2(aV[0][0], F, W0); fma2(aV[0][1], F, W1);
        F = Fv[9];  fma2(aV[1][0], F, W0); fma2(aV[1][1], F, W1);
        F = Fv[10]; fma2(aV[2][0], F, W0); fma2(aV[2][1], F, W1);
#undef LOADP
    }

    float S[4], G[4], V[3][4];
    upk2(aS[0], S[0], S[1]); upk2(aS[1], S[2], S[3]);
    upk2(aG[0], G[0], G[1]); upk2(aG[1], G[2], G[3]);
    #pragma unroll
    for (int k = 0; k < 3; k++) {
        upk2(aV[k][0], V[k][0], V[k][1]);
        upk2(aV[k][1], V[k][2], V[k][3]);
    }

#define RED(v)                                                    \
    v += __shfl_down_sync(0xffffffffu, v, 16);                    \
    v += __shfl_down_sync(0xffffffffu, v, 8);
    #pragma unroll
    for (int q = 0; q < 4; q++) {
        RED(S[q]) RED(G[q]) RED(V[0][q]) RED(V[1][q]) RED(V[2][q])
    }

    if (us == 0) {
        float* na = g_nodeacc + (size_t)dn * 161;
        #pragma unroll
        for (int q = 0; q < 4; q++) {
            int w = wb + q;
            atomicAdd(na + w,              S[q]);
            atomicAdd(na + 32 + w,         G[q]);
            atomicAdd(na + 64 + 3 * w + 0, V[0][q]);
            atomicAdd(na + 64 + 3 * w + 1, V[1][q]);
            atomicAdd(na + 64 + 3 * w + 2, V[2][q]);
        }
        if (lane == 0) atomicAdd(na + 160, 1.0f);
    }
}

// ---------------- kernel 5: mean, gating, self-connection, norms ----------------
__global__ void k_node(const float* __restrict__ x, const float* __restrict__ Wss,
                       const float* __restrict__ Wsv, float* __restrict__ out, int N) {
    __shared__ float sx[8][128];
    const int warp = threadIdx.x >> 5, lane = threadIdx.x & 31;
    int n = blockIdx.x * 8 + warp;
    if (n >= N) return;

    const float4* xr = reinterpret_cast<const float4*>(x + (size_t)n * 128);
    reinterpret_cast<float4*>(&sx[warp][0])[lane] = xr[lane];
    __syncwarp();

    const float* na = g_nodeacc + (size_t)n * 161;
    float inv = 1.0f / fmaxf(na[160], 1.0f);
    float ms  = na[lane] * inv;
    float mg  = na[32 + lane] * inv;
    float mv0 = na[64 + 3 * lane + 0] * inv;
    float mv1 = na[64 + 3 * lane + 1] * inv;
    float mv2 = na[64 + 3 * lane + 2] * inv;

    float gs   = ms / (1.0f + expf(-ms));
    float gate = 1.0f / (1.0f + expf(-mg));
    float gv0 = mv0 * gate, gv1 = mv1 * gate, gv2 = mv2 * gate;

    float ds = 0.f, dv0 = 0.f, dv1 = 0.f, dv2 = 0.f;
    #pragma unroll 4
    for (int u = 0; u < 32; u++) {
        float su  = sx[warp][u];
        float vu0 = sx[warp][32 + 3 * u], vu1 = sx[warp][33 + 3 * u], vu2 = sx[warp][34 + 3 * u];
        float a = __ldg(&Wss[u * 32 + lane]);
        float b = __ldg(&Wsv[u * 32 + lane]);
        ds  = fmaf(su,  a, ds);
        dv0 = fmaf(vu0, b, dv0);
        dv1 = fmaf(vu1, b, dv1);
        dv2 = fmaf(vu2, b, dv2);
    }
    const float ism = 0.17677669529663687f;   // 1/sqrt(32)
    float hs  = gs  + ds  * ism;
    float hv0 = gv0 + dv0 * ism;
    float hv1 = gv1 + dv1 * ism;
    float hv2 = gv2 + dv2 * ism;

    out[(size_t)n * 64 + lane]      = sqrtf(hs * hs + 1e-12f);
    out[(size_t)n * 64 + 32 + lane] = sqrtf(hv0 * hv0 + hv1 * hv1 + hv2 * hv2 + 1e-12f);
}

// ---------------- launch ----------------
extern "C" void kernel_launch(void* const* d_in, const int* in_sizes, int n_in,
                              void* d_out, int out_size) {
    const float* x    = (const float*)d_in[0];
    const float* attr = (const float*)d_in[1];
    const float* len  = (const float*)d_in[2];
    const int*   src  = (const int*)d_in[3];
    const int*   dst  = (const int*)d_in[4];
    const float* Wfc1 = (const float*)d_in[5];
    const float* Wfc2 = (const float*)d_in[6];
    const float* Wss  = (const float*)d_in[7];
    const float* Wsv  = (const float*)d_in[8];
    float* out = (float*)d_out;

    int N = in_sizes[0] / 128;
    int E = in_sizes[2];

    dim3 bgrid(KNOTS / 16, 28);
    k_build<<<bgrid, 256>>>(Wfc1, Wfc2, len, E);                 // #1 (table + hist)
    k_scan<<<1, 32>>>();                                         // #2 (scan + bin reset)
    k_scatterzero<<<(E + 255) / 256, 256>>>(len, E, N * 161);    // #3 (scatter + acc zero)
    k_edge<<<(E + 7) / 8, 256>>>(x, attr, len, src, dst, E);     // #4 (profiled slot)
    k_node<<<(N + 7) / 8, 256>>>(x, Wss, Wsv, out, N);           // #5
}